// round 14
// baseline (speedup 1.0000x reference)
#include <cuda_runtime.h>
#include <cuda_fp16.h>
#include <cstdint>

#define ND 128
#define ED 32
#define HD 256
#define TE 128           // rows per block (M tile), edge + node + pre
#define NTE 256          // 8 warps: 2 in M (64 rows each) x 4 in N
#define LDA_H 264        // A stride in halfs: 528B % 128 == 16 -> conflict-free ldmatrix
#define LDA_HP 136       // pre-kernel A stride in halfs: 272B % 128 == 16
#define LDY 132          // node y-buffer stride in floats (aliases A_h region)
#define WSTRIDE 2048     // B double-buffer stride in float4 (32KB per buffer)

// Scratch (device-resolved symbols only; host shadow address trap!)
__device__ float  g_aggr[(size_t)50176 * ND];
__device__ __half g_Ph[(size_t)50176 * HD];   // fp16: x @ W1[0:128]
__device__ __half g_Qh[(size_t)50176 * HD];   // fp16: x @ W1[128:256]
// fp16 B fragments (m16n8k16 lane order), float4 count = K*N/8
__device__ float4 g_W1ch[ED * HD / 8];        // 1024
__device__ float4 g_W2h[HD * HD / 8];         // 8192
__device__ float4 g_W3h[HD * ND / 8];         // 4096
__device__ float4 g_W1ah[ND * HD / 8];        // 4096
__device__ float4 g_W1bh[ND * HD / 8];        // 4096
__device__ float4 g_Wn1h[HD * HD / 8];        // 8192
__device__ float4 g_Wn2h[HD * ND / 8];        // 4096

__global__ void zero_kernel(int n) {
    int i = blockIdx.x * blockDim.x + threadIdx.x;
    int stride = gridDim.x * blockDim.x;
    for (; i < n; i += stride) g_aggr[i] = 0.0f;
}

// Permute all 7 weight views into fp16 m16n8k16 B-fragment order, 32-row K slabs.
__global__ void perm_all(const float* __restrict__ W1, const float* __restrict__ W2,
                         const float* __restrict__ W3, const float* __restrict__ Wn1,
                         const float* __restrict__ Wn2) {
    int i = blockIdx.x * blockDim.x + threadIdx.x;
    const float* W; uint2* dst; int N;
    int j = i;
    if (j < 2048)                       { W = W1 + 256 * 256; dst = (uint2*)g_W1ch; N = 256; }
    else if ((j -= 2048)  < 16384)      { W = W2;             dst = (uint2*)g_W2h;  N = 256; }
    else if ((j -= 16384) < 8192)       { W = W3;             dst = (uint2*)g_W3h;  N = 128; }
    else if ((j -= 8192)  < 8192)       { W = W1;             dst = (uint2*)g_W1ah; N = 256; }
    else if ((j -= 8192)  < 8192)       { W = W1 + 128 * 256; dst = (uint2*)g_W1bh; N = 256; }
    else if ((j -= 8192)  < 16384)      { W = Wn1;            dst = (uint2*)g_Wn1h; N = 256; }
    else if ((j -= 16384) < 8192)       { W = Wn2;            dst = (uint2*)g_Wn2h; N = 128; }
    else return;
    int l = j & 31;
    int t = j >> 5;
    int nt = t % (N >> 3);
    int q = t / (N >> 3);
    int ks = q & 1, s = q >> 1;
    int k = s * 32 + ks * 16 + (l & 3) * 2;
    int n = nt * 8 + (l >> 2);
    __half2 lo = __floats2half2_rn(W[(size_t)k * N + n],       W[(size_t)(k + 1) * N + n]);
    __half2 hi = __floats2half2_rn(W[(size_t)(k + 8) * N + n], W[(size_t)(k + 9) * N + n]);
    uint2 v;
    v.x = *reinterpret_cast<unsigned*>(&lo);
    v.y = *reinterpret_cast<unsigned*>(&hi);
    dst[j] = v;
}

__device__ __forceinline__ void mma_f16(float (&c)[4], uint32_t a0, uint32_t a1,
                                        uint32_t a2, uint32_t a3, uint32_t b0, uint32_t b1) {
    asm volatile("mma.sync.aligned.m16n8k16.row.col.f32.f16.f16.f32 "
        "{%0,%1,%2,%3}, {%4,%5,%6,%7}, {%8,%9}, {%0,%1,%2,%3};"
        : "+f"(c[0]), "+f"(c[1]), "+f"(c[2]), "+f"(c[3])
        : "r"(a0), "r"(a1), "r"(a2), "r"(a3), "r"(b0), "r"(b1));
}

__device__ __forceinline__ void ldsm4(uint32_t &a0, uint32_t &a1, uint32_t &a2, uint32_t &a3,
                                      const void* p) {
    uint32_t addr = (uint32_t)__cvta_generic_to_shared(p);
    asm volatile("ldmatrix.sync.aligned.m8n8.x4.shared.b16 {%0,%1,%2,%3}, [%4];"
        : "=r"(a0), "=r"(a1), "=r"(a2), "=r"(a3) : "r"(addr));
}

__device__ __forceinline__ void cp_async16(void* smem_dst, const void* gsrc) {
    uint32_t d = (uint32_t)__cvta_generic_to_shared(smem_dst);
    asm volatile("cp.async.cg.shared.global [%0], [%1], 16;" :: "r"(d), "l"(gsrc));
}
__device__ __forceinline__ void cp_commit() { asm volatile("cp.async.commit_group;"); }
__device__ __forceinline__ void cp_wait0()  { asm volatile("cp.async.wait_group 0;" ::: "memory"); }

// fp16 warp-tiled GEMM, 8 warps: wm=wid&1 (64 rows, 4 m-subtiles), wn=wid>>1 (N/4 cols).
// Each B fragment feeds FOUR MMAs -> 32KB/ks crossbar (was 48KB at 16 warps).
// KSLAB-row slabs, double-buffered at WSTRIDE float4; chains into nextBg.
template<int K, int KSLAB, int N, int LDAH>
__device__ __forceinline__ void do_gemm_h(const __half* A_h,
                                          const float4* __restrict__ Wf4,
                                          float4* w_s4, float (&acc)[4][8][4], int tid,
                                          const float4* __restrict__ nextBg, int next4,
                                          int& cur) {
    const int l = tid & 31, wid = tid >> 5;
    const int wm = wid & 1, wn = wid >> 1;
    constexpr int NT8 = N / 8;
    constexpr int NTW = N / 32;             // 8 for N=256, 4 for N=128
    constexpr int SLAB4 = KSLAB * N / 8;
    constexpr int SUB4  = 4 * N;
    constexpr int S = K / KSLAB;
    constexpr int NSUB = KSLAB / 32;

    #pragma unroll
    for (int mt = 0; mt < 4; mt++)
        #pragma unroll
        for (int nt = 0; nt < NTW; nt++)
            #pragma unroll
            for (int i = 0; i < 4; i++) acc[mt][nt][i] = 0.0f;

    const int a_row0 = wm * 64 + ((l >> 3) & 1) * 8 + (l & 7);
    const int a_colh = (l >> 4) * 8;

    #pragma unroll 1
    for (int s = 0; s < S; s++) {
        cp_wait0();
        __syncthreads();          // slab s ready; A_h writes visible
        const float4* src = nullptr; int n4 = 0;
        if (s + 1 < S)   { src = Wf4 + (size_t)(s + 1) * SLAB4; n4 = SLAB4; }
        else if (nextBg) { src = nextBg; n4 = next4; }
        if (src) {
            float4* dst = w_s4 + (cur ^ 1) * WSTRIDE;
            for (int t = tid; t < n4; t += NTE) cp_async16(dst + t, src + t);
            cp_commit();
        }
        const float4* base = w_s4 + cur * WSTRIDE;
        #pragma unroll
        for (int sub = 0; sub < NSUB; sub++) {
            const uint2* wb = (const uint2*)(base + sub * SUB4);
            const int k0 = s * KSLAB + sub * 32;
            #pragma unroll
            for (int ks = 0; ks < 2; ks++) {
                uint2 b[NTW];
                #pragma unroll
                for (int nt = 0; nt < NTW; nt++)
                    b[nt] = wb[(size_t)(ks * NT8 + wn * NTW + nt) * 32 + l];
                #pragma unroll
                for (int mt = 0; mt < 4; mt++) {
                    uint32_t a0, a1, a2, a3;
                    ldsm4(a0, a1, a2, a3,
                          A_h + (a_row0 + mt * 16) * LDAH + k0 + ks * 16 + a_colh);
                    #pragma unroll
                    for (int nt = 0; nt < NTW; nt++)
                        mma_f16(acc[mt][nt], a0, a1, a2, a3, b[nt].x, b[nt].y);
                }
            }
        }
        cur ^= 1;
    }
    __syncthreads();   // all ldsm done before caller rewrites A_h
}

// Epilogue: acc + bias, ReLU, fp16-store to A_h (N=256 layout).
__device__ __forceinline__ void epi_relu_h(float (&acc)[4][8][4], const float* __restrict__ bias,
                                           __half* A_h, int tid) {
    const int l = tid & 31, wid = tid >> 5;
    const int wm = wid & 1, wn = wid >> 1;
    #pragma unroll
    for (int mt = 0; mt < 4; mt++) {
        int r0 = wm * 64 + mt * 16 + (l >> 2);
        #pragma unroll
        for (int nt = 0; nt < 8; nt++) {
            int c0 = (wn * 8 + nt) * 8 + (l & 3) * 2;
            float bb0 = bias[c0], bb1 = bias[c0 + 1];
            *(half2*)(A_h + r0 * LDA_H + c0) =
                __floats2half2_rn(fmaxf(acc[mt][nt][0] + bb0, 0.f),
                                  fmaxf(acc[mt][nt][1] + bb1, 0.f));
            *(half2*)(A_h + (r0 + 8) * LDA_H + c0) =
                __floats2half2_rn(fmaxf(acc[mt][nt][2] + bb0, 0.f),
                                  fmaxf(acc[mt][nt][3] + bb1, 0.f));
        }
    }
}

// Edge pipeline: h1 = relu(ea@W1c + P[row] + Q[col] + b1) -> GEMM2 -> GEMM3 -> scatter.
__global__ __launch_bounds__(NTE, 1) void edge_kernel(
    const float* __restrict__ x, const int* __restrict__ ei,
    const float* __restrict__ ea,
    const float* __restrict__ b1, const float* __restrict__ b2,
    const float* __restrict__ b3,
    int E)
{
    extern __shared__ char smem_c[];
    __half* A_h  = (__half*)smem_c;                       // [TE][LDA_H]
    float4* w_s4 = (float4*)(smem_c + TE * LDA_H * 2);    // 2 x 32KB buffers
    int*    idx_s = (int*)(w_s4 + 2 * WSTRIDE);           // row[TE], col[TE]
    int* row_s = idx_s;
    int* col_s = idx_s + TE;

    const int tid = threadIdx.x;
    const int l = tid & 31, wid = tid >> 5;
    const int wm = wid & 1, wn = wid >> 1;
    const int e0 = blockIdx.x * TE;

    {
        int k = tid & (TE - 1);
        int which = tid >> 7;
        int e = e0 + k;
        idx_s[tid] = (e < E) ? ei[(size_t)which * E + e] : 0;
    }
    __syncthreads();

    // stage W1c (entire, 1024 float4) into buffer 0
    int cur = 0;
    #pragma unroll
    for (int t = tid; t < 1024; t += NTE) cp_async16(w_s4 + t, (const float4*)g_W1ch + t);
    cp_commit();

    // gather ea (K=32, cols 0..31) as fp16
    for (int t = tid; t < TE * 8; t += NTE) {
        int e = t >> 3, j = t & 7;
        float4 v = (e0 + e < E) ? ((const float4*)(ea + (size_t)(e0 + e) * ED))[j]
                                : make_float4(0.f, 0.f, 0.f, 0.f);
        __half* d = A_h + e * LDA_H + j * 4;
        *(half2*)(d)     = __floats2half2_rn(v.x, v.y);
        *(half2*)(d + 2) = __floats2half2_rn(v.z, v.w);
    }

    float acc[4][8][4];

    // GEMM1c: [128,32] x W1c[32,256]  (chains -> W2 superslab 0)
    do_gemm_h<ED, 32, HD, LDA_H>(A_h, g_W1ch, w_s4, acc, tid, (const float4*)g_W2h, 2048, cur);

    // Epilogue 1: acc += P[row] + Q[col] + b1 ; relu ; fp16 store
    #pragma unroll
    for (int mt = 0; mt < 4; mt++) {
        int r0 = wm * 64 + mt * 16 + (l >> 2);
        int r1 = r0 + 8;
        const __half* P0 = g_Ph + (size_t)row_s[r0] * HD;
        const __half* Q0 = g_Qh + (size_t)col_s[r0] * HD;
        const __half* P1 = g_Ph + (size_t)row_s[r1] * HD;
        const __half* Q1 = g_Qh + (size_t)col_s[r1] * HD;
        #pragma unroll
        for (int nt = 0; nt < 8; nt++) {
            int c0 = (wn * 8 + nt) * 8 + (l & 3) * 2;
            float2 p0 = __half22float2(*(const half2*)(P0 + c0));
            float2 q0 = __half22float2(*(const half2*)(Q0 + c0));
            float2 p1 = __half22float2(*(const half2*)(P1 + c0));
            float2 q1 = __half22float2(*(const half2*)(Q1 + c0));
            float bb0 = b1[c0], bb1 = b1[c0 + 1];
            *(half2*)(A_h + r0 * LDA_H + c0) =
                __floats2half2_rn(fmaxf(acc[mt][nt][0] + p0.x + q0.x + bb0, 0.f),
                                  fmaxf(acc[mt][nt][1] + p0.y + q0.y + bb1, 0.f));
            *(half2*)(A_h + r1 * LDA_H + c0) =
                __floats2half2_rn(fmaxf(acc[mt][nt][2] + p1.x + q1.x + bb0, 0.f),
                                  fmaxf(acc[mt][nt][3] + p1.y + q1.y + bb1, 0.f));
        }
    }

    // GEMM2: [128,256] x W2, K=64 superslabs  (chains -> W3 superslab 0)
    do_gemm_h<HD, 64, HD, LDA_H>(A_h, g_W2h, w_s4, acc, tid, (const float4*)g_W3h, 1024, cur);
    epi_relu_h(acc, b2, A_h, tid);

    // GEMM3: [128,256] x W3[256,128] -> +b3 -> scatter-add
    do_gemm_h<HD, 64, ND, LDA_H>(A_h, g_W3h, w_s4, acc, tid, nullptr, 0, cur);
    #pragma unroll
    for (int mt = 0; mt < 4; mt++) {
        int r0 = wm * 64 + mt * 16 + (l >> 2);
        int r1 = r0 + 8;
        bool ok0 = (e0 + r0) < E, ok1 = (e0 + r1) < E;
        float* dst0 = g_aggr + (size_t)col_s[r0] * ND;
        float* dst1 = g_aggr + (size_t)col_s[r1] * ND;
        #pragma unroll
        for (int nt = 0; nt < 4; nt++) {
            int c0 = (wn * 4 + nt) * 8 + (l & 3) * 2;
            float bb0 = b3[c0], bb1 = b3[c0 + 1];
            if (ok0) {
                atomicAdd(dst0 + c0,     acc[mt][nt][0] + bb0);
                atomicAdd(dst0 + c0 + 1, acc[mt][nt][1] + bb1);
            }
            if (ok1) {
                atomicAdd(dst1 + c0,     acc[mt][nt][2] + bb0);
                atomicAdd(dst1 + c0 + 1, acc[mt][nt][3] + bb1);
            }
        }
    }
}

// Precompute P = x@W1a, Q = x@W1b per 128-node tile (fp16 out; bias added later).
__global__ __launch_bounds__(NTE, 1) void pre_kernel(const float* __restrict__ x, int Nn)
{
    extern __shared__ char smem_c[];
    __half* A_h  = (__half*)smem_c;                       // [TE][LDA_HP]
    float4* w_s4 = (float4*)(smem_c + TE * LDA_HP * 2);

    const int tid = threadIdx.x;
    const int l = tid & 31, wid = tid >> 5;
    const int wm = wid & 1, wn = wid >> 1;
    const int n0 = blockIdx.x * TE;

    int cur = 0;
    #pragma unroll
    for (int t = tid; t < 2048; t += NTE) cp_async16(w_s4 + t, (const float4*)g_W1ah + t);
    cp_commit();

    for (int t = tid; t < TE * 32; t += NTE) {
        int r = t >> 5, j = t & 31;
        int n = n0 + r; if (n >= Nn) n = Nn - 1;
        float4 v = ((const float4*)(x + (size_t)n * ND))[j];
        __half* d = A_h + r * LDA_HP + j * 4;
        *(half2*)(d)     = __floats2half2_rn(v.x, v.y);
        *(half2*)(d + 2) = __floats2half2_rn(v.z, v.w);
    }

    float acc[4][8][4];
    #pragma unroll 1
    for (int which = 0; which < 2; which++) {
        if (which == 0)
            do_gemm_h<ND, 64, HD, LDA_HP>(A_h, g_W1ah, w_s4, acc, tid,
                                          (const float4*)g_W1bh, 2048, cur);
        else
            do_gemm_h<ND, 64, HD, LDA_HP>(A_h, g_W1bh, w_s4, acc, tid, nullptr, 0, cur);
        __half* O = which ? g_Qh : g_Ph;
        #pragma unroll
        for (int mt = 0; mt < 4; mt++) {
            int r0 = wm * 64 + mt * 16 + (l >> 2);
            int nr0 = n0 + r0, nr1 = nr0 + 8;
            #pragma unroll
            for (int nt = 0; nt < 8; nt++) {
                int c0 = (wn * 8 + nt) * 8 + (l & 3) * 2;
                if (nr0 < Nn) *(half2*)(O + (size_t)nr0 * HD + c0) =
                    __floats2half2_rn(acc[mt][nt][0], acc[mt][nt][1]);
                if (nr1 < Nn) *(half2*)(O + (size_t)nr1 * HD + c0) =
                    __floats2half2_rn(acc[mt][nt][2], acc[mt][nt][3]);
            }
        }
    }
}

// Node pipeline (fp16 MMA): [x|aggr] -> relu(.@Wn1+bn1) -> .@Wn2+bn2 -> +x -> LayerNorm.
__global__ __launch_bounds__(NTE, 1) void node_kernel(
    const float* __restrict__ x,
    const float* __restrict__ bn1, const float* __restrict__ bn2,
    const float* __restrict__ gamma, const float* __restrict__ beta,
    float* __restrict__ out, int Nn)
{
    extern __shared__ char smem_c[];
    __half* A_h  = (__half*)smem_c;                       // [TE][LDA_H]
    float*  y_s  = (float*)smem_c;                        // [TE][LDY] fp32, aliases A_h
    float4* w_s4 = (float4*)(smem_c + TE * LDA_H * 2);

    const int tid = threadIdx.x;
    const int l = tid & 31, wid = tid >> 5;
    const int wm = wid & 1, wn = wid >> 1;
    const int n0 = blockIdx.x * TE;

    int cur = 0;
    #pragma unroll
    for (int t = tid; t < 2048; t += NTE) cp_async16(w_s4 + t, (const float4*)g_Wn1h + t);
    cp_commit();

    for (int t = tid; t < TE * 64; t += NTE) {
        int r = t >> 6, j = t & 63;
        int n = n0 + r; if (n >= Nn) n = Nn - 1;
        float4 v = (j < 32) ? ((const float4*)(x + (size_t)n * ND))[j]
                            : ((const float4*)(g_aggr + (size_t)n * ND))[j - 32];
        __half* d = A_h + r * LDA_H + j * 4;
        *(half2*)(d)     = __floats2half2_rn(v.x, v.y);
        *(half2*)(d + 2) = __floats2half2_rn(v.z, v.w);
    }

    float acc[4][8][4];

    // GEMM_n1: [128,256] x Wn1 -> relu -> A_h  (chains -> Wn2)
    do_gemm_h<HD, 64, HD, LDA_H>(A_h, g_Wn1h, w_s4, acc, tid, (const float4*)g_Wn2h, 1024, cur);
    epi_relu_h(acc, bn1, A_h, tid);

    // GEMM_n2: [128,256] x Wn2[256,128] -> +bn2 +x -> y_s fp32
    do_gemm_h<HD, 64, ND, LDA_H>(A_h, g_Wn2h, w_s4, acc, tid, nullptr, 0, cur);
    #pragma unroll
    for (int mt = 0; mt < 4; mt++) {
        int r0 = wm * 64 + mt * 16 + (l >> 2);
        int r1 = r0 + 8;
        int nr0 = n0 + r0; if (nr0 >= Nn) nr0 = Nn - 1;
        int nr1 = n0 + r1; if (nr1 >= Nn) nr1 = Nn - 1;
        #pragma unroll
        for (int nt = 0; nt < 4; nt++) {
            int c0 = (wn * 4 + nt) * 8 + (l & 3) * 2;
            float2 x0 = *(const float2*)(x + (size_t)nr0 * ND + c0);
            float2 x1 = *(const float2*)(x + (size_t)nr1 * ND + c0);
            float bb0 = bn2[c0], bb1 = bn2[c0 + 1];
            y_s[r0 * LDY + c0]     = acc[mt][nt][0] + bb0 + x0.x;
            y_s[r0 * LDY + c0 + 1] = acc[mt][nt][1] + bb1 + x0.y;
            y_s[r1 * LDY + c0]     = acc[mt][nt][2] + bb0 + x1.x;
            y_s[r1 * LDY + c0 + 1] = acc[mt][nt][3] + bb1 + x1.y;
        }
    }
    __syncthreads();

    // LayerNorm: warp wid handles rows wid*16 .. wid*16+15
    #pragma unroll 1
    for (int rr = 0; rr < 16; rr++) {
        int r = wid * 16 + rr;
        float4 v = *(const float4*)(y_s + r * LDY + l * 4);
        float s  = v.x + v.y + v.z + v.w;
        float sq = v.x * v.x + v.y * v.y + v.z * v.z + v.w * v.w;
        #pragma unroll
        for (int o = 16; o > 0; o >>= 1) {
            s  += __shfl_xor_sync(0xffffffffu, s, o);
            sq += __shfl_xor_sync(0xffffffffu, sq, o);
        }
        float mean = s * (1.0f / ND);
        float var  = sq * (1.0f / ND) - mean * mean;
        float rstd = rsqrtf(var + 1e-5f);
        int n = n0 + r;
        if (n < Nn) {
            float4 g  = ((const float4*)gamma)[l];
            float4 bb = ((const float4*)beta)[l];
            float4 o4;
            o4.x = (v.x - mean) * rstd * g.x + bb.x;
            o4.y = (v.y - mean) * rstd * g.y + bb.y;
            o4.z = (v.z - mean) * rstd * g.z + bb.z;
            o4.w = (v.w - mean) * rstd * g.w + bb.w;
            ((float4*)(out + (size_t)n * ND))[l] = o4;
        }
    }
}

extern "C" void kernel_launch(void* const* d_in, const int* in_sizes, int n_in,
                              void* d_out, int out_size) {
    const float* x   = (const float*)d_in[0];
    const int*   ei  = (const int*)d_in[1];
    const float* ea  = (const float*)d_in[2];
    const float* W1  = (const float*)d_in[3];
    const float* b1  = (const float*)d_in[4];
    const float* W2  = (const float*)d_in[5];
    const float* b2  = (const float*)d_in[6];
    const float* W3  = (const float*)d_in[7];
    const float* b3  = (const float*)d_in[8];
    const float* Wn1 = (const float*)d_in[9];
    const float* bn1 = (const float*)d_in[10];
    const float* Wn2 = (const float*)d_in[11];
    const float* bn2 = (const float*)d_in[12];
    const float* gm  = (const float*)d_in[13];
    const float* bt  = (const float*)d_in[14];
    float* out = (float*)d_out;

    const int N = in_sizes[0] / ND;
    const int E = in_sizes[1] / 2;

    const int EDGE_SMEM = TE * LDA_H * 2 + 2 * WSTRIDE * 16 + 2 * TE * 4;  // ~132 KB
    const int PRE_SMEM  = TE * LDA_HP * 2 + 2 * WSTRIDE * 16;              // ~99 KB
    const int NODE_SMEM = TE * LDA_H * 2 + 2 * WSTRIDE * 16;               // ~130 KB
    cudaFuncSetAttribute(edge_kernel, cudaFuncAttributeMaxDynamicSharedMemorySize, EDGE_SMEM);
    cudaFuncSetAttribute(pre_kernel,  cudaFuncAttributeMaxDynamicSharedMemorySize, PRE_SMEM);
    cudaFuncSetAttribute(node_kernel, cudaFuncAttributeMaxDynamicSharedMemorySize, NODE_SMEM);

    int zero_blocks = (N * ND + 255) / 256;
    if (zero_blocks > 4096) zero_blocks = 4096;

    zero_kernel<<<zero_blocks, 256>>>(N * ND);
    perm_all<<<(67584 + 255) / 256, 256>>>(W1, W2, W3, Wn1, Wn2);
    pre_kernel<<<(N + TE - 1) / TE, NTE, PRE_SMEM>>>(x, N);
    edge_kernel<<<(E + TE - 1) / TE, NTE, EDGE_SMEM>>>(x, ei, ea, b1, b2, b3, E);
    node_kernel<<<(N + TE - 1) / TE, NTE, NODE_SMEM>>>(x, bn1, bn2, gm, bt, out, N);
}

// round 15
// speedup vs baseline: 1.0325x; 1.0325x over previous
#include <cuda_runtime.h>
#include <cuda_fp16.h>
#include <cstdint>

#define ND 128
#define ED 32
#define HD 256
#define TE 128           // rows per block (M tile), edge + node + pre
#define NTE 256          // 8 warps: 2 in M (64 rows each) x 4 in N
#define LDA_H 264        // A stride in halfs: 528B % 128 == 16 -> conflict-free ldmatrix
#define LDA_HP 136       // pre-kernel A stride in halfs: 272B % 128 == 16
#define LDY 132          // node y-buffer stride in floats (aliases A_h region)
#define WSTRIDE 4096     // B double-buffer stride in float4 (64KB per buffer)

// Scratch (device-resolved symbols only; host shadow address trap!)
__device__ float  g_aggr[(size_t)50176 * ND];
__device__ __half g_Ph[(size_t)50176 * HD];   // fp16: x @ W1[0:128]
__device__ __half g_Qh[(size_t)50176 * HD];   // fp16: x @ W1[128:256]
// fp16 B fragments (m16n8k16 lane order), float4 count = K*N/8
__device__ float4 g_W1ch[ED * HD / 8];        // 1024
__device__ float4 g_W2h[HD * HD / 8];         // 8192
__device__ float4 g_W3h[HD * ND / 8];         // 4096
__device__ float4 g_W1ah[ND * HD / 8];        // 4096
__device__ float4 g_W1bh[ND * HD / 8];        // 4096
__device__ float4 g_Wn1h[HD * HD / 8];        // 8192
__device__ float4 g_Wn2h[HD * ND / 8];        // 4096

__global__ void zero_kernel(int n) {
    int i = blockIdx.x * blockDim.x + threadIdx.x;
    int stride = gridDim.x * blockDim.x;
    for (; i < n; i += stride) g_aggr[i] = 0.0f;
}

// Permute all 7 weight views into fp16 m16n8k16 B-fragment order, 32-row K slabs
// (contiguous slabs compose into K=64/128 superslabs without layout change).
__global__ void perm_all(const float* __restrict__ W1, const float* __restrict__ W2,
                         const float* __restrict__ W3, const float* __restrict__ Wn1,
                         const float* __restrict__ Wn2) {
    int i = blockIdx.x * blockDim.x + threadIdx.x;
    const float* W; uint2* dst; int N;
    int j = i;
    if (j < 2048)                       { W = W1 + 256 * 256; dst = (uint2*)g_W1ch; N = 256; }
    else if ((j -= 2048)  < 16384)      { W = W2;             dst = (uint2*)g_W2h;  N = 256; }
    else if ((j -= 16384) < 8192)       { W = W3;             dst = (uint2*)g_W3h;  N = 128; }
    else if ((j -= 8192)  < 8192)       { W = W1;             dst = (uint2*)g_W1ah; N = 256; }
    else if ((j -= 8192)  < 8192)       { W = W1 + 128 * 256; dst = (uint2*)g_W1bh; N = 256; }
    else if ((j -= 8192)  < 16384)      { W = Wn1;            dst = (uint2*)g_Wn1h; N = 256; }
    else if ((j -= 16384) < 8192)       { W = Wn2;            dst = (uint2*)g_Wn2h; N = 128; }
    else return;
    int l = j & 31;
    int t = j >> 5;
    int nt = t % (N >> 3);
    int q = t / (N >> 3);
    int ks = q & 1, s = q >> 1;
    int k = s * 32 + ks * 16 + (l & 3) * 2;
    int n = nt * 8 + (l >> 2);
    __half2 lo = __floats2half2_rn(W[(size_t)k * N + n],       W[(size_t)(k + 1) * N + n]);
    __half2 hi = __floats2half2_rn(W[(size_t)(k + 8) * N + n], W[(size_t)(k + 9) * N + n]);
    uint2 v;
    v.x = *reinterpret_cast<unsigned*>(&lo);
    v.y = *reinterpret_cast<unsigned*>(&hi);
    dst[j] = v;
}

__device__ __forceinline__ void mma_f16(float (&c)[4], uint32_t a0, uint32_t a1,
                                        uint32_t a2, uint32_t a3, uint32_t b0, uint32_t b1) {
    asm volatile("mma.sync.aligned.m16n8k16.row.col.f32.f16.f16.f32 "
        "{%0,%1,%2,%3}, {%4,%5,%6,%7}, {%8,%9}, {%0,%1,%2,%3};"
        : "+f"(c[0]), "+f"(c[1]), "+f"(c[2]), "+f"(c[3])
        : "r"(a0), "r"(a1), "r"(a2), "r"(a3), "r"(b0), "r"(b1));
}

__device__ __forceinline__ void ldsm4(uint32_t &a0, uint32_t &a1, uint32_t &a2, uint32_t &a3,
                                      const void* p) {
    uint32_t addr = (uint32_t)__cvta_generic_to_shared(p);
    asm volatile("ldmatrix.sync.aligned.m8n8.x4.shared.b16 {%0,%1,%2,%3}, [%4];"
        : "=r"(a0), "=r"(a1), "=r"(a2), "=r"(a3) : "r"(addr));
}

__device__ __forceinline__ void cp_async16(void* smem_dst, const void* gsrc) {
    uint32_t d = (uint32_t)__cvta_generic_to_shared(smem_dst);
    asm volatile("cp.async.cg.shared.global [%0], [%1], 16;" :: "r"(d), "l"(gsrc));
}
__device__ __forceinline__ void cp_commit() { asm volatile("cp.async.commit_group;"); }
__device__ __forceinline__ void cp_wait0()  { asm volatile("cp.async.wait_group 0;" ::: "memory"); }

// fp16 warp-tiled GEMM, 8 warps: wm=wid&1 (64 rows, 4 m-subtiles), wn=wid>>1 (N/4 cols).
// Each B fragment feeds FOUR MMAs. KSLAB-row superslabs (KSLAB/32 contiguous
// 32-subslabs), double-buffered at WSTRIDE float4; chains into nextBg's first
// slab. Caller stages the first slab into buffer `cur`; cur carried across GEMMs.
template<int K, int KSLAB, int N, int LDAH>
__device__ __forceinline__ void do_gemm_h(const __half* A_h,
                                          const float4* __restrict__ Wf4,
                                          float4* w_s4, float (&acc)[4][8][4], int tid,
                                          const float4* __restrict__ nextBg, int next4,
                                          int& cur) {
    const int l = tid & 31, wid = tid >> 5;
    const int wm = wid & 1, wn = wid >> 1;
    constexpr int NT8 = N / 8;
    constexpr int NTW = N / 32;             // 8 for N=256, 4 for N=128
    constexpr int SLAB4 = KSLAB * N / 8;
    constexpr int SUB4  = 4 * N;
    constexpr int S = K / KSLAB;
    constexpr int NSUB = KSLAB / 32;

    #pragma unroll
    for (int mt = 0; mt < 4; mt++)
        #pragma unroll
        for (int nt = 0; nt < NTW; nt++)
            #pragma unroll
            for (int i = 0; i < 4; i++) acc[mt][nt][i] = 0.0f;

    const int a_row0 = wm * 64 + ((l >> 3) & 1) * 8 + (l & 7);
    const int a_colh = (l >> 4) * 8;

    #pragma unroll 1
    for (int s = 0; s < S; s++) {
        cp_wait0();
        __syncthreads();          // slab s ready; A_h writes visible
        const float4* src = nullptr; int n4 = 0;
        if (s + 1 < S)   { src = Wf4 + (size_t)(s + 1) * SLAB4; n4 = SLAB4; }
        else if (nextBg) { src = nextBg; n4 = next4; }
        if (src) {
            float4* dst = w_s4 + (cur ^ 1) * WSTRIDE;
            for (int t = tid; t < n4; t += NTE) cp_async16(dst + t, src + t);
            cp_commit();
        }
        const float4* base = w_s4 + cur * WSTRIDE;
        #pragma unroll
        for (int sub = 0; sub < NSUB; sub++) {
            const uint2* wb = (const uint2*)(base + sub * SUB4);
            const int k0 = s * KSLAB + sub * 32;
            #pragma unroll
            for (int ks = 0; ks < 2; ks++) {
                uint2 b[NTW];
                #pragma unroll
                for (int nt = 0; nt < NTW; nt++)
                    b[nt] = wb[(size_t)(ks * NT8 + wn * NTW + nt) * 32 + l];
                #pragma unroll
                for (int mt = 0; mt < 4; mt++) {
                    uint32_t a0, a1, a2, a3;
                    ldsm4(a0, a1, a2, a3,
                          A_h + (a_row0 + mt * 16) * LDAH + k0 + ks * 16 + a_colh);
                    #pragma unroll
                    for (int nt = 0; nt < NTW; nt++)
                        mma_f16(acc[mt][nt], a0, a1, a2, a3, b[nt].x, b[nt].y);
                }
            }
        }
        cur ^= 1;
    }
    __syncthreads();   // all ldsm done before caller rewrites A_h
}

// Epilogue: acc + bias, ReLU, fp16-store to A_h (N=256 layout).
__device__ __forceinline__ void epi_relu_h(float (&acc)[4][8][4], const float* __restrict__ bias,
                                           __half* A_h, int tid) {
    const int l = tid & 31, wid = tid >> 5;
    const int wm = wid & 1, wn = wid >> 1;
    #pragma unroll
    for (int mt = 0; mt < 4; mt++) {
        int r0 = wm * 64 + mt * 16 + (l >> 2);
        #pragma unroll
        for (int nt = 0; nt < 8; nt++) {
            int c0 = (wn * 8 + nt) * 8 + (l & 3) * 2;
            float bb0 = bias[c0], bb1 = bias[c0 + 1];
            *(half2*)(A_h + r0 * LDA_H + c0) =
                __floats2half2_rn(fmaxf(acc[mt][nt][0] + bb0, 0.f),
                                  fmaxf(acc[mt][nt][1] + bb1, 0.f));
            *(half2*)(A_h + (r0 + 8) * LDA_H + c0) =
                __floats2half2_rn(fmaxf(acc[mt][nt][2] + bb0, 0.f),
                                  fmaxf(acc[mt][nt][3] + bb1, 0.f));
        }
    }
}

// Edge pipeline: h1 = relu(ea@W1c + P[row] + Q[col] + b1) -> GEMM2 -> GEMM3 -> scatter.
__global__ __launch_bounds__(NTE, 1) void edge_kernel(
    const float* __restrict__ x, const int* __restrict__ ei,
    const float* __restrict__ ea,
    const float* __restrict__ b1, const float* __restrict__ b2,
    const float* __restrict__ b3,
    int E)
{
    extern __shared__ char smem_c[];
    __half* A_h  = (__half*)smem_c;                       // [TE][LDA_H]
    float4* w_s4 = (float4*)(smem_c + TE * LDA_H * 2);    // 2 x 64KB buffers
    int*    idx_s = (int*)(w_s4 + 2 * WSTRIDE);           // row[TE], col[TE]
    int* row_s = idx_s;
    int* col_s = idx_s + TE;

    const int tid = threadIdx.x;
    const int l = tid & 31, wid = tid >> 5;
    const int wm = wid & 1, wn = wid >> 1;
    const int e0 = blockIdx.x * TE;

    {
        int k = tid & (TE - 1);
        int which = tid >> 7;
        int e = e0 + k;
        idx_s[tid] = (e < E) ? ei[(size_t)which * E + e] : 0;
    }
    __syncthreads();

    // stage W1c (entire, 1024 float4) into buffer 0
    int cur = 0;
    #pragma unroll
    for (int t = tid; t < 1024; t += NTE) cp_async16(w_s4 + t, (const float4*)g_W1ch + t);
    cp_commit();

    // gather ea (K=32, cols 0..31) as fp16
    for (int t = tid; t < TE * 8; t += NTE) {
        int e = t >> 3, j = t & 7;
        float4 v = (e0 + e < E) ? ((const float4*)(ea + (size_t)(e0 + e) * ED))[j]
                                : make_float4(0.f, 0.f, 0.f, 0.f);
        __half* d = A_h + e * LDA_H + j * 4;
        *(half2*)(d)     = __floats2half2_rn(v.x, v.y);
        *(half2*)(d + 2) = __floats2half2_rn(v.z, v.w);
    }

    float acc[4][8][4];

    // GEMM1c: [128,32] x W1c[32,256]  (chains -> W2 superslab 0, 64KB)
    do_gemm_h<ED, 32, HD, LDA_H>(A_h, g_W1ch, w_s4, acc, tid, (const float4*)g_W2h, 4096, cur);

    // Epilogue 1: acc += P[row] + Q[col] + b1 ; relu ; fp16 store
    #pragma unroll
    for (int mt = 0; mt < 4; mt++) {
        int r0 = wm * 64 + mt * 16 + (l >> 2);
        int r1 = r0 + 8;
        const __half* P0 = g_Ph + (size_t)row_s[r0] * HD;
        const __half* Q0 = g_Qh + (size_t)col_s[r0] * HD;
        const __half* P1 = g_Ph + (size_t)row_s[r1] * HD;
        const __half* Q1 = g_Qh + (size_t)col_s[r1] * HD;
        #pragma unroll
        for (int nt = 0; nt < 8; nt++) {
            int c0 = (wn * 8 + nt) * 8 + (l & 3) * 2;
            float2 p0 = __half22float2(*(const half2*)(P0 + c0));
            float2 q0 = __half22float2(*(const half2*)(Q0 + c0));
            float2 p1 = __half22float2(*(const half2*)(P1 + c0));
            float2 q1 = __half22float2(*(const half2*)(Q1 + c0));
            float bb0 = b1[c0], bb1 = b1[c0 + 1];
            *(half2*)(A_h + r0 * LDA_H + c0) =
                __floats2half2_rn(fmaxf(acc[mt][nt][0] + p0.x + q0.x + bb0, 0.f),
                                  fmaxf(acc[mt][nt][1] + p0.y + q0.y + bb1, 0.f));
            *(half2*)(A_h + r1 * LDA_H + c0) =
                __floats2half2_rn(fmaxf(acc[mt][nt][2] + p1.x + q1.x + bb0, 0.f),
                                  fmaxf(acc[mt][nt][3] + p1.y + q1.y + bb1, 0.f));
        }
    }

    // GEMM2: [128,256] x W2, K=128 superslabs (2 syncs; chains -> W3 slab 0)
    do_gemm_h<HD, 128, HD, LDA_H>(A_h, g_W2h, w_s4, acc, tid, (const float4*)g_W3h, 2048, cur);
    epi_relu_h(acc, b2, A_h, tid);

    // GEMM3: [128,256] x W3[256,128], K=128 superslabs -> +b3 -> scatter-add
    do_gemm_h<HD, 128, ND, LDA_H>(A_h, g_W3h, w_s4, acc, tid, nullptr, 0, cur);
    #pragma unroll
    for (int mt = 0; mt < 4; mt++) {
        int r0 = wm * 64 + mt * 16 + (l >> 2);
        int r1 = r0 + 8;
        bool ok0 = (e0 + r0) < E, ok1 = (e0 + r1) < E;
        float* dst0 = g_aggr + (size_t)col_s[r0] * ND;
        float* dst1 = g_aggr + (size_t)col_s[r1] * ND;
        #pragma unroll
        for (int nt = 0; nt < 4; nt++) {
            int c0 = (wn * 4 + nt) * 8 + (l & 3) * 2;
            float bb0 = b3[c0], bb1 = b3[c0 + 1];
            if (ok0) {
                atomicAdd(dst0 + c0,     acc[mt][nt][0] + bb0);
                atomicAdd(dst0 + c0 + 1, acc[mt][nt][1] + bb1);
            }
            if (ok1) {
                atomicAdd(dst1 + c0,     acc[mt][nt][2] + bb0);
                atomicAdd(dst1 + c0 + 1, acc[mt][nt][3] + bb1);
            }
        }
    }
}

// Precompute P = x@W1a, Q = x@W1b per 128-node tile (fp16 out; bias added later).
__global__ __launch_bounds__(NTE, 1) void pre_kernel(const float* __restrict__ x, int Nn)
{
    extern __shared__ char smem_c[];
    __half* A_h  = (__half*)smem_c;                       // [TE][LDA_HP]
    float4* w_s4 = (float4*)(smem_c + TE * LDA_HP * 2);

    const int tid = threadIdx.x;
    const int l = tid & 31, wid = tid >> 5;
    const int wm = wid & 1, wn = wid >> 1;
    const int n0 = blockIdx.x * TE;

    int cur = 0;
    #pragma unroll
    for (int t = tid; t < 4096; t += NTE) cp_async16(w_s4 + t, (const float4*)g_W1ah + t);
    cp_commit();

    for (int t = tid; t < TE * 32; t += NTE) {
        int r = t >> 5, j = t & 31;
        int n = n0 + r; if (n >= Nn) n = Nn - 1;
        float4 v = ((const float4*)(x + (size_t)n * ND))[j];
        __half* d = A_h + r * LDA_HP + j * 4;
        *(half2*)(d)     = __floats2half2_rn(v.x, v.y);
        *(half2*)(d + 2) = __floats2half2_rn(v.z, v.w);
    }

    float acc[4][8][4];
    #pragma unroll 1
    for (int which = 0; which < 2; which++) {
        if (which == 0)
            do_gemm_h<ND, 128, HD, LDA_HP>(A_h, g_W1ah, w_s4, acc, tid,
                                           (const float4*)g_W1bh, 4096, cur);
        else
            do_gemm_h<ND, 128, HD, LDA_HP>(A_h, g_W1bh, w_s4, acc, tid, nullptr, 0, cur);
        __half* O = which ? g_Qh : g_Ph;
        #pragma unroll
        for (int mt = 0; mt < 4; mt++) {
            int r0 = wm * 64 + mt * 16 + (l >> 2);
            int nr0 = n0 + r0, nr1 = nr0 + 8;
            #pragma unroll
            for (int nt = 0; nt < 8; nt++) {
                int c0 = (wn * 8 + nt) * 8 + (l & 3) * 2;
                if (nr0 < Nn) *(half2*)(O + (size_t)nr0 * HD + c0) =
                    __floats2half2_rn(acc[mt][nt][0], acc[mt][nt][1]);
                if (nr1 < Nn) *(half2*)(O + (size_t)nr1 * HD + c0) =
                    __floats2half2_rn(acc[mt][nt][2], acc[mt][nt][3]);
            }
        }
    }
}

// Node pipeline (fp16 MMA): [x|aggr] -> relu(.@Wn1+bn1) -> .@Wn2+bn2 -> +x -> LayerNorm.
__global__ __launch_bounds__(NTE, 1) void node_kernel(
    const float* __restrict__ x,
    const float* __restrict__ bn1, const float* __restrict__ bn2,
    const float* __restrict__ gamma, const float* __restrict__ beta,
    float* __restrict__ out, int Nn)
{
    extern __shared__ char smem_c[];
    __half* A_h  = (__half*)smem_c;                       // [TE][LDA_H]
    float*  y_s  = (float*)smem_c;                        // [TE][LDY] fp32, aliases A_h
    float4* w_s4 = (float4*)(smem_c + TE * LDA_H * 2);

    const int tid = threadIdx.x;
    const int l = tid & 31, wid = tid >> 5;
    const int wm = wid & 1, wn = wid >> 1;
    const int n0 = blockIdx.x * TE;

    int cur = 0;
    #pragma unroll
    for (int t = tid; t < 4096; t += NTE) cp_async16(w_s4 + t, (const float4*)g_Wn1h + t);
    cp_commit();

    for (int t = tid; t < TE * 64; t += NTE) {
        int r = t >> 6, j = t & 63;
        int n = n0 + r; if (n >= Nn) n = Nn - 1;
        float4 v = (j < 32) ? ((const float4*)(x + (size_t)n * ND))[j]
                            : ((const float4*)(g_aggr + (size_t)n * ND))[j - 32];
        __half* d = A_h + r * LDA_H + j * 4;
        *(half2*)(d)     = __floats2half2_rn(v.x, v.y);
        *(half2*)(d + 2) = __floats2half2_rn(v.z, v.w);
    }

    float acc[4][8][4];

    // GEMM_n1: [128,256] x Wn1, K=128 superslabs -> relu -> A_h  (chains -> Wn2)
    do_gemm_h<HD, 128, HD, LDA_H>(A_h, g_Wn1h, w_s4, acc, tid, (const float4*)g_Wn2h, 2048, cur);
    epi_relu_h(acc, bn1, A_h, tid);

    // GEMM_n2: [128,256] x Wn2[256,128], K=128 -> +bn2 +x -> y_s fp32
    do_gemm_h<HD, 128, ND, LDA_H>(A_h, g_Wn2h, w_s4, acc, tid, nullptr, 0, cur);
    #pragma unroll
    for (int mt = 0; mt < 4; mt++) {
        int r0 = wm * 64 + mt * 16 + (l >> 2);
        int r1 = r0 + 8;
        int nr0 = n0 + r0; if (nr0 >= Nn) nr0 = Nn - 1;
        int nr1 = n0 + r1; if (nr1 >= Nn) nr1 = Nn - 1;
        #pragma unroll
        for (int nt = 0; nt < 4; nt++) {
            int c0 = (wn * 4 + nt) * 8 + (l & 3) * 2;
            float2 x0 = *(const float2*)(x + (size_t)nr0 * ND + c0);
            float2 x1 = *(const float2*)(x + (size_t)nr1 * ND + c0);
            float bb0 = bn2[c0], bb1 = bn2[c0 + 1];
            y_s[r0 * LDY + c0]     = acc[mt][nt][0] + bb0 + x0.x;
            y_s[r0 * LDY + c0 + 1] = acc[mt][nt][1] + bb1 + x0.y;
            y_s[r1 * LDY + c0]     = acc[mt][nt][2] + bb0 + x1.x;
            y_s[r1 * LDY + c0 + 1] = acc[mt][nt][3] + bb1 + x1.y;
        }
    }
    __syncthreads();

    // LayerNorm: warp wid handles rows wid*16 .. wid*16+15
    #pragma unroll 1
    for (int rr = 0; rr < 16; rr++) {
        int r = wid * 16 + rr;
        float4 v = *(const float4*)(y_s + r * LDY + l * 4);
        float s  = v.x + v.y + v.z + v.w;
        float sq = v.x * v.x + v.y * v.y + v.z * v.z + v.w * v.w;
        #pragma unroll
        for (int o = 16; o > 0; o >>= 1) {
            s  += __shfl_xor_sync(0xffffffffu, s, o);
            sq += __shfl_xor_sync(0xffffffffu, sq, o);
        }
        float mean = s * (1.0f / ND);
        float var  = sq * (1.0f / ND) - mean * mean;
        float rstd = rsqrtf(var + 1e-5f);
        int n = n0 + r;
        if (n < Nn) {
            float4 g  = ((const float4*)gamma)[l];
            float4 bb = ((const float4*)beta)[l];
            float4 o4;
            o4.x = (v.x - mean) * rstd * g.x + bb.x;
            o4.y = (v.y - mean) * rstd * g.y + bb.y;
            o4.z = (v.z - mean) * rstd * g.z + bb.z;
            o4.w = (v.w - mean) * rstd * g.w + bb.w;
            ((float4*)(out + (size_t)n * ND))[l] = o4;
        }
    }
}

extern "C" void kernel_launch(void* const* d_in, const int* in_sizes, int n_in,
                              void* d_out, int out_size) {
    const float* x   = (const float*)d_in[0];
    const int*   ei  = (const int*)d_in[1];
    const float* ea  = (const float*)d_in[2];
    const float* W1  = (const float*)d_in[3];
    const float* b1  = (const float*)d_in[4];
    const float* W2  = (const float*)d_in[5];
    const float* b2  = (const float*)d_in[6];
    const float* W3  = (const float*)d_in[7];
    const float* b3  = (const float*)d_in[8];
    const float* Wn1 = (const float*)d_in[9];
    const float* bn1 = (const float*)d_in[10];
    const float* Wn2 = (const float*)d_in[11];
    const float* bn2 = (const float*)d_in[12];
    const float* gm  = (const float*)d_in[13];
    const float* bt  = (const float*)d_in[14];
    float* out = (float*)d_out;

    const int N = in_sizes[0] / ND;
    const int E = in_sizes[1] / 2;

    const int EDGE_SMEM = TE * LDA_H * 2 + 2 * WSTRIDE * 16 + 2 * TE * 4;  // ~196 KB
    const int PRE_SMEM  = TE * LDA_HP * 2 + 2 * WSTRIDE * 16;              // ~163 KB
    const int NODE_SMEM = TE * LDA_H * 2 + 2 * WSTRIDE * 16;               // ~195 KB
    cudaFuncSetAttribute(edge_kernel, cudaFuncAttributeMaxDynamicSharedMemorySize, EDGE_SMEM);
    cudaFuncSetAttribute(pre_kernel,  cudaFuncAttributeMaxDynamicSharedMemorySize, PRE_SMEM);
    cudaFuncSetAttribute(node_kernel, cudaFuncAttributeMaxDynamicSharedMemorySize, NODE_SMEM);

    int zero_blocks = (N * ND + 255) / 256;
    if (zero_blocks > 4096) zero_blocks = 4096;

    zero_kernel<<<zero_blocks, 256>>>(N * ND);
    perm_all<<<(67584 + 255) / 256, 256>>>(W1, W2, W3, Wn1, Wn2);
    pre_kernel<<<(N + TE - 1) / TE, NTE, PRE_SMEM>>>(x, N);
    edge_kernel<<<(E + TE - 1) / TE, NTE, EDGE_SMEM>>>(x, ei, ea, b1, b2, b3, E);
    node_kernel<<<(N + TE - 1) / TE, NTE, NODE_SMEM>>>(x, bn1, bn2, gm, bt, out, N);
}

// round 16
// speedup vs baseline: 1.0856x; 1.0515x over previous
#include <cuda_runtime.h>
#include <cuda_fp16.h>
#include <cstdint>

#define ND 128
#define ED 32
#define HD 256
#define TE 128           // rows per block (M tile), edge + node + pre
#define NTE 256          // 8 warps: 2 in M (64 rows each) x 4 in N
#define LDA_H 264        // A stride in halfs: 528B % 128 == 16 -> conflict-free ldmatrix
#define LDA_HP 136       // pre-kernel A stride in halfs
#define LDY 132          // node y-buffer stride in floats (aliases A_h region)

// Scratch (device-resolved symbols only; host shadow address trap!)
__device__ float  g_aggr[(size_t)50176 * ND];
__device__ __half g_Ph[(size_t)50176 * HD];   // fp16: x @ W1[0:128]
__device__ __half g_Qh[(size_t)50176 * HD];   // fp16: x @ W1[128:256]
// fp16 B fragments (m16n8k16 lane order); L2-resident, read directly via LDG.
__device__ float4 g_W1ch[ED * HD / 8];        // 1024
__device__ float4 g_W2h[HD * HD / 8];         // 8192
__device__ float4 g_W3h[HD * ND / 8];         // 4096
__device__ float4 g_W1ah[ND * HD / 8];        // 4096
__device__ float4 g_W1bh[ND * HD / 8];        // 4096
__device__ float4 g_Wn1h[HD * HD / 8];        // 8192
__device__ float4 g_Wn2h[HD * ND / 8];        // 4096

__global__ void zero_kernel(int n) {
    int i = blockIdx.x * blockDim.x + threadIdx.x;
    int stride = gridDim.x * blockDim.x;
    for (; i < n; i += stride) g_aggr[i] = 0.0f;
}

// Permute all 7 weight views into fp16 m16n8k16 B-fragment order.
// uint2 index j = (g*NT8 + nt)*32 + l, g = K/16 step index.
__global__ void perm_all(const float* __restrict__ W1, const float* __restrict__ W2,
                         const float* __restrict__ W3, const float* __restrict__ Wn1,
                         const float* __restrict__ Wn2) {
    int i = blockIdx.x * blockDim.x + threadIdx.x;
    const float* W; uint2* dst; int N;
    int j = i;
    if (j < 2048)                       { W = W1 + 256 * 256; dst = (uint2*)g_W1ch; N = 256; }
    else if ((j -= 2048)  < 16384)      { W = W2;             dst = (uint2*)g_W2h;  N = 256; }
    else if ((j -= 16384) < 8192)       { W = W3;             dst = (uint2*)g_W3h;  N = 128; }
    else if ((j -= 8192)  < 8192)       { W = W1;             dst = (uint2*)g_W1ah; N = 256; }
    else if ((j -= 8192)  < 8192)       { W = W1 + 128 * 256; dst = (uint2*)g_W1bh; N = 256; }
    else if ((j -= 8192)  < 16384)      { W = Wn1;            dst = (uint2*)g_Wn1h; N = 256; }
    else if ((j -= 16384) < 8192)       { W = Wn2;            dst = (uint2*)g_Wn2h; N = 128; }
    else return;
    int l = j & 31;
    int t = j >> 5;
    int nt = t % (N >> 3);
    int g = t / (N >> 3);               // K/16 step
    int k = g * 16 + (l & 3) * 2;
    int n = nt * 8 + (l >> 2);
    __half2 lo = __floats2half2_rn(W[(size_t)k * N + n],       W[(size_t)(k + 1) * N + n]);
    __half2 hi = __floats2half2_rn(W[(size_t)(k + 8) * N + n], W[(size_t)(k + 9) * N + n]);
    uint2 v;
    v.x = *reinterpret_cast<unsigned*>(&lo);
    v.y = *reinterpret_cast<unsigned*>(&hi);
    dst[j] = v;
}

__device__ __forceinline__ void mma_f16(float (&c)[4], uint32_t a0, uint32_t a1,
                                        uint32_t a2, uint32_t a3, uint32_t b0, uint32_t b1) {
    asm volatile("mma.sync.aligned.m16n8k16.row.col.f32.f16.f16.f32 "
        "{%0,%1,%2,%3}, {%4,%5,%6,%7}, {%8,%9}, {%0,%1,%2,%3};"
        : "+f"(c[0]), "+f"(c[1]), "+f"(c[2]), "+f"(c[3])
        : "r"(a0), "r"(a1), "r"(a2), "r"(a3), "r"(b0), "r"(b1));
}

__device__ __forceinline__ void ldsm4(uint32_t &a0, uint32_t &a1, uint32_t &a2, uint32_t &a3,
                                      const void* p) {
    uint32_t addr = (uint32_t)__cvta_generic_to_shared(p);
    asm volatile("ldmatrix.sync.aligned.m8n8.x4.shared.b16 {%0,%1,%2,%3}, [%4];"
        : "=r"(a0), "=r"(a1), "=r"(a2), "=r"(a3) : "r"(addr));
}

// fp16 warp-tiled GEMM, 8 warps: wm=wid&1 (64 rows, 4 m-subtiles), wn=wid>>1 (N/4 cols).
// B fragments read DIRECTLY from L2-resident global fragments (no smem staging,
// no barriers in the mainloop), register-double-buffered one K16-step ahead.
// A resident in smem (written before call; trailing syncthreads protects rewrite).
template<int K, int N, int LDAH>
__device__ __forceinline__ void do_gemm_g(const __half* A_h,
                                          const uint2* __restrict__ Wg,
                                          float (&acc)[4][8][4], int tid) {
    const int l = tid & 31, wid = tid >> 5;
    const int wm = wid & 1, wn = wid >> 1;
    constexpr int NT8 = N / 8;
    constexpr int NTW = N / 32;             // 8 for N=256, 4 for N=128
    constexpr int NKS = K / 16;

    #pragma unroll
    for (int mt = 0; mt < 4; mt++)
        #pragma unroll
        for (int nt = 0; nt < NTW; nt++)
            #pragma unroll
            for (int i = 0; i < 4; i++) acc[mt][nt][i] = 0.0f;

    const int a_row0 = wm * 64 + ((l >> 3) & 1) * 8 + (l & 7);
    const int a_colh = (l >> 4) * 8;
    const uint2* wbase = Wg + (size_t)(wn * NTW) * 32 + l;

    uint2 b[2][NTW];
    #pragma unroll
    for (int nt = 0; nt < NTW; nt++) b[0][nt] = __ldg(wbase + nt * 32);

    #pragma unroll
    for (int g = 0; g < NKS; g++) {
        const int cb = g & 1, nb = cb ^ 1;
        if (g + 1 < NKS) {
            #pragma unroll
            for (int nt = 0; nt < NTW; nt++)
                b[nb][nt] = __ldg(wbase + (size_t)((g + 1) * NT8 + nt) * 32);
        }
        #pragma unroll
        for (int mt = 0; mt < 4; mt++) {
            uint32_t a0, a1, a2, a3;
            ldsm4(a0, a1, a2, a3, A_h + (a_row0 + mt * 16) * LDAH + g * 16 + a_colh);
            #pragma unroll
            for (int nt = 0; nt < NTW; nt++)
                mma_f16(acc[mt][nt], a0, a1, a2, a3, b[cb][nt].x, b[cb][nt].y);
        }
    }
    __syncthreads();   // all ldsm done before caller rewrites A_h
}

// Epilogue: acc + bias, ReLU, fp16-store to A_h (N=256 layout).
__device__ __forceinline__ void epi_relu_h(float (&acc)[4][8][4], const float* __restrict__ bias,
                                           __half* A_h, int tid) {
    const int l = tid & 31, wid = tid >> 5;
    const int wm = wid & 1, wn = wid >> 1;
    #pragma unroll
    for (int mt = 0; mt < 4; mt++) {
        int r0 = wm * 64 + mt * 16 + (l >> 2);
        #pragma unroll
        for (int nt = 0; nt < 8; nt++) {
            int c0 = (wn * 8 + nt) * 8 + (l & 3) * 2;
            float bb0 = bias[c0], bb1 = bias[c0 + 1];
            *(half2*)(A_h + r0 * LDA_H + c0) =
                __floats2half2_rn(fmaxf(acc[mt][nt][0] + bb0, 0.f),
                                  fmaxf(acc[mt][nt][1] + bb1, 0.f));
            *(half2*)(A_h + (r0 + 8) * LDA_H + c0) =
                __floats2half2_rn(fmaxf(acc[mt][nt][2] + bb0, 0.f),
                                  fmaxf(acc[mt][nt][3] + bb1, 0.f));
        }
    }
    __syncthreads();   // A_h fully written before next GEMM's ldsm
}

// Edge pipeline: h1 = relu(ea@W1c + P[row] + Q[col] + b1) -> GEMM2 -> GEMM3 -> scatter.
__global__ __launch_bounds__(NTE, 1) void edge_kernel(
    const float* __restrict__ x, const int* __restrict__ ei,
    const float* __restrict__ ea,
    const float* __restrict__ b1, const float* __restrict__ b2,
    const float* __restrict__ b3,
    int E)
{
    extern __shared__ char smem_c[];
    __half* A_h  = (__half*)smem_c;                       // [TE][LDA_H]
    int*    idx_s = (int*)(smem_c + TE * LDA_H * 2);      // row[TE], col[TE]
    int* row_s = idx_s;
    int* col_s = idx_s + TE;

    const int tid = threadIdx.x;
    const int l = tid & 31, wid = tid >> 5;
    const int wm = wid & 1, wn = wid >> 1;
    const int e0 = blockIdx.x * TE;

    {
        int k = tid & (TE - 1);
        int which = tid >> 7;
        int e = e0 + k;
        idx_s[tid] = (e < E) ? ei[(size_t)which * E + e] : 0;
    }

    // gather ea (K=32, cols 0..31) as fp16
    for (int t = tid; t < TE * 8; t += NTE) {
        int e = t >> 3, j = t & 7;
        float4 v = (e0 + e < E) ? ((const float4*)(ea + (size_t)(e0 + e) * ED))[j]
                                : make_float4(0.f, 0.f, 0.f, 0.f);
        __half* d = A_h + e * LDA_H + j * 4;
        *(half2*)(d)     = __floats2half2_rn(v.x, v.y);
        *(half2*)(d + 2) = __floats2half2_rn(v.z, v.w);
    }
    __syncthreads();

    float acc[4][8][4];

    // GEMM1c: [128,32] x W1c[32,256]
    do_gemm_g<ED, HD, LDA_H>(A_h, (const uint2*)g_W1ch, acc, tid);

    // Epilogue 1: acc += P[row] + Q[col] + b1 ; relu ; fp16 store
    #pragma unroll
    for (int mt = 0; mt < 4; mt++) {
        int r0 = wm * 64 + mt * 16 + (l >> 2);
        int r1 = r0 + 8;
        const __half* P0 = g_Ph + (size_t)row_s[r0] * HD;
        const __half* Q0 = g_Qh + (size_t)col_s[r0] * HD;
        const __half* P1 = g_Ph + (size_t)row_s[r1] * HD;
        const __half* Q1 = g_Qh + (size_t)col_s[r1] * HD;
        #pragma unroll
        for (int nt = 0; nt < 8; nt++) {
            int c0 = (wn * 8 + nt) * 8 + (l & 3) * 2;
            float2 p0 = __half22float2(*(const half2*)(P0 + c0));
            float2 q0 = __half22float2(*(const half2*)(Q0 + c0));
            float2 p1 = __half22float2(*(const half2*)(P1 + c0));
            float2 q1 = __half22float2(*(const half2*)(Q1 + c0));
            float bb0 = b1[c0], bb1 = b1[c0 + 1];
            *(half2*)(A_h + r0 * LDA_H + c0) =
                __floats2half2_rn(fmaxf(acc[mt][nt][0] + p0.x + q0.x + bb0, 0.f),
                                  fmaxf(acc[mt][nt][1] + p0.y + q0.y + bb1, 0.f));
            *(half2*)(A_h + r1 * LDA_H + c0) =
                __floats2half2_rn(fmaxf(acc[mt][nt][2] + p1.x + q1.x + bb0, 0.f),
                                  fmaxf(acc[mt][nt][3] + p1.y + q1.y + bb1, 0.f));
        }
    }
    __syncthreads();

    // GEMM2: [128,256] x W2
    do_gemm_g<HD, HD, LDA_H>(A_h, (const uint2*)g_W2h, acc, tid);
    epi_relu_h(acc, b2, A_h, tid);

    // GEMM3: [128,256] x W3[256,128] -> +b3 -> scatter-add (acc-register epilogue)
    do_gemm_g<HD, ND, LDA_H>(A_h, (const uint2*)g_W3h, acc, tid);
    #pragma unroll
    for (int mt = 0; mt < 4; mt++) {
        int r0 = wm * 64 + mt * 16 + (l >> 2);
        int r1 = r0 + 8;
        bool ok0 = (e0 + r0) < E, ok1 = (e0 + r1) < E;
        float* dst0 = g_aggr + (size_t)col_s[r0] * ND;
        float* dst1 = g_aggr + (size_t)col_s[r1] * ND;
        #pragma unroll
        for (int nt = 0; nt < 4; nt++) {
            int c0 = (wn * 4 + nt) * 8 + (l & 3) * 2;
            float bb0 = b3[c0], bb1 = b3[c0 + 1];
            if (ok0) {
                atomicAdd(dst0 + c0,     acc[mt][nt][0] + bb0);
                atomicAdd(dst0 + c0 + 1, acc[mt][nt][1] + bb1);
            }
            if (ok1) {
                atomicAdd(dst1 + c0,     acc[mt][nt][2] + bb0);
                atomicAdd(dst1 + c0 + 1, acc[mt][nt][3] + bb1);
            }
        }
    }
}

// Precompute P = x@W1a, Q = x@W1b per 128-node tile (fp16 out; bias added later).
__global__ __launch_bounds__(NTE, 1) void pre_kernel(const float* __restrict__ x, int Nn)
{
    extern __shared__ char smem_c[];
    __half* A_h = (__half*)smem_c;                        // [TE][LDA_HP]

    const int tid = threadIdx.x;
    const int l = tid & 31, wid = tid >> 5;
    const int wm = wid & 1, wn = wid >> 1;
    const int n0 = blockIdx.x * TE;

    for (int t = tid; t < TE * 32; t += NTE) {
        int r = t >> 5, j = t & 31;
        int n = n0 + r; if (n >= Nn) n = Nn - 1;
        float4 v = ((const float4*)(x + (size_t)n * ND))[j];
        __half* d = A_h + r * LDA_HP + j * 4;
        *(half2*)(d)     = __floats2half2_rn(v.x, v.y);
        *(half2*)(d + 2) = __floats2half2_rn(v.z, v.w);
    }
    __syncthreads();

    float acc[4][8][4];
    #pragma unroll 1
    for (int which = 0; which < 2; which++) {
        do_gemm_g<ND, HD, LDA_HP>(A_h, which ? (const uint2*)g_W1bh : (const uint2*)g_W1ah,
                                  acc, tid);
        __half* O = which ? g_Qh : g_Ph;
        #pragma unroll
        for (int mt = 0; mt < 4; mt++) {
            int r0 = wm * 64 + mt * 16 + (l >> 2);
            int nr0 = n0 + r0, nr1 = nr0 + 8;
            #pragma unroll
            for (int nt = 0; nt < 8; nt++) {
                int c0 = (wn * 8 + nt) * 8 + (l & 3) * 2;
                if (nr0 < Nn) *(half2*)(O + (size_t)nr0 * HD + c0) =
                    __floats2half2_rn(acc[mt][nt][0], acc[mt][nt][1]);
                if (nr1 < Nn) *(half2*)(O + (size_t)nr1 * HD + c0) =
                    __floats2half2_rn(acc[mt][nt][2], acc[mt][nt][3]);
            }
        }
    }
}

// Node pipeline (fp16 MMA): [x|aggr] -> relu(.@Wn1+bn1) -> .@Wn2+bn2 -> +x -> LayerNorm.
__global__ __launch_bounds__(NTE, 1) void node_kernel(
    const float* __restrict__ x,
    const float* __restrict__ bn1, const float* __restrict__ bn2,
    const float* __restrict__ gamma, const float* __restrict__ beta,
    float* __restrict__ out, int Nn)
{
    extern __shared__ char smem_c[];
    __half* A_h = (__half*)smem_c;                        // [TE][LDA_H]
    float*  y_s = (float*)smem_c;                         // [TE][LDY] fp32, aliases A_h

    const int tid = threadIdx.x;
    const int l = tid & 31, wid = tid >> 5;
    const int wm = wid & 1, wn = wid >> 1;
    const int n0 = blockIdx.x * TE;

    for (int t = tid; t < TE * 64; t += NTE) {
        int r = t >> 6, j = t & 63;
        int n = n0 + r; if (n >= Nn) n = Nn - 1;
        float4 v = (j < 32) ? ((const float4*)(x + (size_t)n * ND))[j]
                            : ((const float4*)(g_aggr + (size_t)n * ND))[j - 32];
        __half* d = A_h + r * LDA_H + j * 4;
        *(half2*)(d)     = __floats2half2_rn(v.x, v.y);
        *(half2*)(d + 2) = __floats2half2_rn(v.z, v.w);
    }
    __syncthreads();

    float acc[4][8][4];

    // GEMM_n1: [128,256] x Wn1 -> relu -> A_h
    do_gemm_g<HD, HD, LDA_H>(A_h, (const uint2*)g_Wn1h, acc, tid);
    epi_relu_h(acc, bn1, A_h, tid);

    // GEMM_n2: [128,256] x Wn2[256,128] -> +bn2 +x -> y_s fp32
    do_gemm_g<HD, ND, LDA_H>(A_h, (const uint2*)g_Wn2h, acc, tid);
    #pragma unroll
    for (int mt = 0; mt < 4; mt++) {
        int r0 = wm * 64 + mt * 16 + (l >> 2);
        int r1 = r0 + 8;
        int nr0 = n0 + r0; if (nr0 >= Nn) nr0 = Nn - 1;
        int nr1 = n0 + r1; if (nr1 >= Nn) nr1 = Nn - 1;
        #pragma unroll
        for (int nt = 0; nt < 4; nt++) {
            int c0 = (wn * 4 + nt) * 8 + (l & 3) * 2;
            float2 x0 = *(const float2*)(x + (size_t)nr0 * ND + c0);
            float2 x1 = *(const float2*)(x + (size_t)nr1 * ND + c0);
            float bb0 = bn2[c0], bb1 = bn2[c0 + 1];
            y_s[r0 * LDY + c0]     = acc[mt][nt][0] + bb0 + x0.x;
            y_s[r0 * LDY + c0 + 1] = acc[mt][nt][1] + bb1 + x0.y;
            y_s[r1 * LDY + c0]     = acc[mt][nt][2] + bb0 + x1.x;
            y_s[r1 * LDY + c0 + 1] = acc[mt][nt][3] + bb1 + x1.y;
        }
    }
    __syncthreads();

    // LayerNorm: warp wid handles rows wid*16 .. wid*16+15
    #pragma unroll 1
    for (int rr = 0; rr < 16; rr++) {
        int r = wid * 16 + rr;
        float4 v = *(const float4*)(y_s + r * LDY + l * 4);
        float s  = v.x + v.y + v.z + v.w;
        float sq = v.x * v.x + v.y * v.y + v.z * v.z + v.w * v.w;
        #pragma unroll
        for (int o = 16; o > 0; o >>= 1) {
            s  += __shfl_xor_sync(0xffffffffu, s, o);
            sq += __shfl_xor_sync(0xffffffffu, sq, o);
        }
        float mean = s * (1.0f / ND);
        float var  = sq * (1.0f / ND) - mean * mean;
        float rstd = rsqrtf(var + 1e-5f);
        int n = n0 + r;
        if (n < Nn) {
            float4 g  = ((const float4*)gamma)[l];
            float4 bb = ((const float4*)beta)[l];
            float4 o4;
            o4.x = (v.x - mean) * rstd * g.x + bb.x;
            o4.y = (v.y - mean) * rstd * g.y + bb.y;
            o4.z = (v.z - mean) * rstd * g.z + bb.z;
            o4.w = (v.w - mean) * rstd * g.w + bb.w;
            ((float4*)(out + (size_t)n * ND))[l] = o4;
        }
    }
}

extern "C" void kernel_launch(void* const* d_in, const int* in_sizes, int n_in,
                              void* d_out, int out_size) {
    const float* x   = (const float*)d_in[0];
    const int*   ei  = (const int*)d_in[1];
    const float* ea  = (const float*)d_in[2];
    const float* W1  = (const float*)d_in[3];
    const float* b1  = (const float*)d_in[4];
    const float* W2  = (const float*)d_in[5];
    const float* b2  = (const float*)d_in[6];
    const float* W3  = (const float*)d_in[7];
    const float* b3  = (const float*)d_in[8];
    const float* Wn1 = (const float*)d_in[9];
    const float* bn1 = (const float*)d_in[10];
    const float* Wn2 = (const float*)d_in[11];
    const float* bn2 = (const float*)d_in[12];
    const float* gm  = (const float*)d_in[13];
    const float* bt  = (const float*)d_in[14];
    float* out = (float*)d_out;

    const int N = in_sizes[0] / ND;
    const int E = in_sizes[1] / 2;

    const int EDGE_SMEM = TE * LDA_H * 2 + 2 * TE * 4;    // ~68.6 KB
    const int PRE_SMEM  = TE * LDA_HP * 2;                // ~34.8 KB
    const int NODE_SMEM = TE * LDA_H * 2;                 // ~67.6 KB
    cudaFuncSetAttribute(edge_kernel, cudaFuncAttributeMaxDynamicSharedMemorySize, EDGE_SMEM);
    cudaFuncSetAttribute(pre_kernel,  cudaFuncAttributeMaxDynamicSharedMemorySize, PRE_SMEM);
    cudaFuncSetAttribute(node_kernel, cudaFuncAttributeMaxDynamicSharedMemorySize, NODE_SMEM);

    int zero_blocks = (N * ND + 255) / 256;
    if (zero_blocks > 4096) zero_blocks = 4096;

    zero_kernel<<<zero_blocks, 256>>>(N * ND);
    perm_all<<<(67584 + 255) / 256, 256>>>(W1, W2, W3, Wn1, Wn2);
    pre_kernel<<<(N + TE - 1) / TE, NTE, PRE_SMEM>>>(x, N);
    edge_kernel<<<(E + TE - 1) / TE, NTE, EDGE_SMEM>>>(x, ei, ea, b1, b2, b3, E);
    node_kernel<<<(N + TE - 1) / TE, NTE, NODE_SMEM>>>(x, bn1, bn2, gm, bt, out, N);
}

// round 17
// speedup vs baseline: 1.2126x; 1.1169x over previous
#include <cuda_runtime.h>
#include <cuda_fp16.h>
#include <cstdint>

#define ND 128
#define ED 32
#define HD 256
#define TE 128           // rows per block for pre/node
#define TE_E 64          // edges per block (edge kernel, 2 CTAs/SM)
#define NTE 256          // 8 warps
#define LDA_H 264        // A stride in halfs: 528B % 128 == 16 -> conflict-free ldmatrix
#define LDA_HP 136       // pre-kernel A stride in halfs
#define LDY 132          // node y-buffer stride in floats (aliases A_h region)

// Scratch (device-resolved symbols only; host shadow address trap!)
__device__ float  g_aggr[(size_t)50176 * ND];
__device__ __half g_Ph[(size_t)50176 * HD];   // fp16: x @ W1[0:128]
__device__ __half g_Qh[(size_t)50176 * HD];   // fp16: x @ W1[128:256]
// fp16 B fragments (m16n8k16 lane order); L2-resident, read directly via LDG.
__device__ float4 g_W1ch[ED * HD / 8];        // 1024
__device__ float4 g_W2h[HD * HD / 8];         // 8192
__device__ float4 g_W3h[HD * ND / 8];         // 4096
__device__ float4 g_W1ah[ND * HD / 8];        // 4096
__device__ float4 g_W1bh[ND * HD / 8];        // 4096
__device__ float4 g_Wn1h[HD * HD / 8];        // 8192
__device__ float4 g_Wn2h[HD * ND / 8];        // 4096

__global__ void zero_kernel(int n) {
    int i = blockIdx.x * blockDim.x + threadIdx.x;
    int stride = gridDim.x * blockDim.x;
    for (; i < n; i += stride) g_aggr[i] = 0.0f;
}

// Permute all 7 weight views into fp16 m16n8k16 B-fragment order.
// uint2 index j = (g*NT8 + nt)*32 + l, g = K/16 step index.
__global__ void perm_all(const float* __restrict__ W1, const float* __restrict__ W2,
                         const float* __restrict__ W3, const float* __restrict__ Wn1,
                         const float* __restrict__ Wn2) {
    int i = blockIdx.x * blockDim.x + threadIdx.x;
    const float* W; uint2* dst; int N;
    int j = i;
    if (j < 2048)                       { W = W1 + 256 * 256; dst = (uint2*)g_W1ch; N = 256; }
    else if ((j -= 2048)  < 16384)      { W = W2;             dst = (uint2*)g_W2h;  N = 256; }
    else if ((j -= 16384) < 8192)       { W = W3;             dst = (uint2*)g_W3h;  N = 128; }
    else if ((j -= 8192)  < 8192)       { W = W1;             dst = (uint2*)g_W1ah; N = 256; }
    else if ((j -= 8192)  < 8192)       { W = W1 + 128 * 256; dst = (uint2*)g_W1bh; N = 256; }
    else if ((j -= 8192)  < 16384)      { W = Wn1;            dst = (uint2*)g_Wn1h; N = 256; }
    else if ((j -= 16384) < 8192)       { W = Wn2;            dst = (uint2*)g_Wn2h; N = 128; }
    else return;
    int l = j & 31;
    int t = j >> 5;
    int nt = t % (N >> 3);
    int g = t / (N >> 3);               // K/16 step
    int k = g * 16 + (l & 3) * 2;
    int n = nt * 8 + (l >> 2);
    __half2 lo = __floats2half2_rn(W[(size_t)k * N + n],       W[(size_t)(k + 1) * N + n]);
    __half2 hi = __floats2half2_rn(W[(size_t)(k + 8) * N + n], W[(size_t)(k + 9) * N + n]);
    uint2 v;
    v.x = *reinterpret_cast<unsigned*>(&lo);
    v.y = *reinterpret_cast<unsigned*>(&hi);
    dst[j] = v;
}

__device__ __forceinline__ void mma_f16(float (&c)[4], uint32_t a0, uint32_t a1,
                                        uint32_t a2, uint32_t a3, uint32_t b0, uint32_t b1) {
    asm volatile("mma.sync.aligned.m16n8k16.row.col.f32.f16.f16.f32 "
        "{%0,%1,%2,%3}, {%4,%5,%6,%7}, {%8,%9}, {%0,%1,%2,%3};"
        : "+f"(c[0]), "+f"(c[1]), "+f"(c[2]), "+f"(c[3])
        : "r"(a0), "r"(a1), "r"(a2), "r"(a3), "r"(b0), "r"(b1));
}

__device__ __forceinline__ void ldsm4(uint32_t &a0, uint32_t &a1, uint32_t &a2, uint32_t &a3,
                                      const void* p) {
    uint32_t addr = (uint32_t)__cvta_generic_to_shared(p);
    asm volatile("ldmatrix.sync.aligned.m8n8.x4.shared.b16 {%0,%1,%2,%3}, [%4];"
        : "=r"(a0), "=r"(a1), "=r"(a2), "=r"(a3) : "r"(addr));
}

// fp16 warp-tiled GEMM, 8 warps: wm=wid&1 (MT*16 rows), wn=wid>>1 (N/4 cols).
// B fragments read directly from L2-resident globals, register-double-buffered
// one K16-step ahead. A resident in smem. No barriers in the mainloop.
template<int MT, int K, int N, int LDAH>
__device__ __forceinline__ void do_gemm_g(const __half* A_h,
                                          const uint2* __restrict__ Wg,
                                          float (&acc)[MT][8][4], int tid) {
    const int l = tid & 31, wid = tid >> 5;
    const int wm = wid & 1, wn = wid >> 1;
    constexpr int NT8 = N / 8;
    constexpr int NTW = N / 32;             // 8 for N=256, 4 for N=128
    constexpr int NKS = K / 16;

    #pragma unroll
    for (int mt = 0; mt < MT; mt++)
        #pragma unroll
        for (int nt = 0; nt < NTW; nt++)
            #pragma unroll
            for (int i = 0; i < 4; i++) acc[mt][nt][i] = 0.0f;

    const int a_row0 = wm * (MT * 16) + ((l >> 3) & 1) * 8 + (l & 7);
    const int a_colh = (l >> 4) * 8;
    const uint2* wbase = Wg + (size_t)(wn * NTW) * 32 + l;

    uint2 b[2][NTW];
    #pragma unroll
    for (int nt = 0; nt < NTW; nt++) b[0][nt] = __ldg(wbase + nt * 32);

    #pragma unroll
    for (int g = 0; g < NKS; g++) {
        const int cb = g & 1, nb = cb ^ 1;
        if (g + 1 < NKS) {
            #pragma unroll
            for (int nt = 0; nt < NTW; nt++)
                b[nb][nt] = __ldg(wbase + (size_t)((g + 1) * NT8 + nt) * 32);
        }
        #pragma unroll
        for (int mt = 0; mt < MT; mt++) {
            uint32_t a0, a1, a2, a3;
            ldsm4(a0, a1, a2, a3, A_h + (a_row0 + mt * 16) * LDAH + g * 16 + a_colh);
            #pragma unroll
            for (int nt = 0; nt < NTW; nt++)
                mma_f16(acc[mt][nt], a0, a1, a2, a3, b[cb][nt].x, b[cb][nt].y);
        }
    }
    __syncthreads();   // all ldsm done before caller rewrites A_h
}

// Epilogue: acc + bias, ReLU, fp16-store to A_h (N=256 layout).
template<int MT>
__device__ __forceinline__ void epi_relu_h(float (&acc)[MT][8][4], const float* __restrict__ bias,
                                           __half* A_h, int tid) {
    const int l = tid & 31, wid = tid >> 5;
    const int wm = wid & 1, wn = wid >> 1;
    #pragma unroll
    for (int mt = 0; mt < MT; mt++) {
        int r0 = wm * (MT * 16) + mt * 16 + (l >> 2);
        #pragma unroll
        for (int nt = 0; nt < 8; nt++) {
            int c0 = (wn * 8 + nt) * 8 + (l & 3) * 2;
            float bb0 = bias[c0], bb1 = bias[c0 + 1];
            *(half2*)(A_h + r0 * LDA_H + c0) =
                __floats2half2_rn(fmaxf(acc[mt][nt][0] + bb0, 0.f),
                                  fmaxf(acc[mt][nt][1] + bb1, 0.f));
            *(half2*)(A_h + (r0 + 8) * LDA_H + c0) =
                __floats2half2_rn(fmaxf(acc[mt][nt][2] + bb0, 0.f),
                                  fmaxf(acc[mt][nt][3] + bb1, 0.f));
        }
    }
    __syncthreads();   // A_h fully written before next GEMM's ldsm
}

// Edge pipeline (TE_E=64, 2 CTAs/SM): h1 = relu(ea@W1c + P[row] + Q[col] + b1)
// -> GEMM2 -> GEMM3 -> scatter.
__global__ __launch_bounds__(NTE, 2) void edge_kernel(
    const float* __restrict__ x, const int* __restrict__ ei,
    const float* __restrict__ ea,
    const float* __restrict__ b1, const float* __restrict__ b2,
    const float* __restrict__ b3,
    int E)
{
    extern __shared__ char smem_c[];
    __half* A_h  = (__half*)smem_c;                       // [TE_E][LDA_H]
    int*    idx_s = (int*)(smem_c + TE_E * LDA_H * 2);    // row[TE_E], col[TE_E]
    int* row_s = idx_s;
    int* col_s = idx_s + TE_E;

    const int tid = threadIdx.x;
    const int l = tid & 31, wid = tid >> 5;
    const int wm = wid & 1, wn = wid >> 1;
    const int e0 = blockIdx.x * TE_E;

    if (tid < 2 * TE_E) {
        int k = tid & (TE_E - 1);
        int which = tid >> 6;
        int e = e0 + k;
        idx_s[tid] = (e < E) ? ei[(size_t)which * E + e] : 0;
    }

    // gather ea (K=32, cols 0..31) as fp16
    for (int t = tid; t < TE_E * 8; t += NTE) {
        int e = t >> 3, j = t & 7;
        float4 v = (e0 + e < E) ? ((const float4*)(ea + (size_t)(e0 + e) * ED))[j]
                                : make_float4(0.f, 0.f, 0.f, 0.f);
        __half* d = A_h + e * LDA_H + j * 4;
        *(half2*)(d)     = __floats2half2_rn(v.x, v.y);
        *(half2*)(d + 2) = __floats2half2_rn(v.z, v.w);
    }
    __syncthreads();

    float acc[2][8][4];

    // GEMM1c: [64,32] x W1c[32,256]
    do_gemm_g<2, ED, HD, LDA_H>(A_h, (const uint2*)g_W1ch, acc, tid);

    // Epilogue 1: acc += P[row] + Q[col] + b1 ; relu ; fp16 store
    #pragma unroll
    for (int mt = 0; mt < 2; mt++) {
        int r0 = wm * 32 + mt * 16 + (l >> 2);
        int r1 = r0 + 8;
        const __half* P0 = g_Ph + (size_t)row_s[r0] * HD;
        const __half* Q0 = g_Qh + (size_t)col_s[r0] * HD;
        const __half* P1 = g_Ph + (size_t)row_s[r1] * HD;
        const __half* Q1 = g_Qh + (size_t)col_s[r1] * HD;
        #pragma unroll
        for (int nt = 0; nt < 8; nt++) {
            int c0 = (wn * 8 + nt) * 8 + (l & 3) * 2;
            float2 p0 = __half22float2(*(const half2*)(P0 + c0));
            float2 q0 = __half22float2(*(const half2*)(Q0 + c0));
            float2 p1 = __half22float2(*(const half2*)(P1 + c0));
            float2 q1 = __half22float2(*(const half2*)(Q1 + c0));
            float bb0 = b1[c0], bb1 = b1[c0 + 1];
            *(half2*)(A_h + r0 * LDA_H + c0) =
                __floats2half2_rn(fmaxf(acc[mt][nt][0] + p0.x + q0.x + bb0, 0.f),
                                  fmaxf(acc[mt][nt][1] + p0.y + q0.y + bb1, 0.f));
            *(half2*)(A_h + r1 * LDA_H + c0) =
                __floats2half2_rn(fmaxf(acc[mt][nt][2] + p1.x + q1.x + bb0, 0.f),
                                  fmaxf(acc[mt][nt][3] + p1.y + q1.y + bb1, 0.f));
        }
    }
    __syncthreads();

    // GEMM2: [64,256] x W2
    do_gemm_g<2, HD, HD, LDA_H>(A_h, (const uint2*)g_W2h, acc, tid);
    epi_relu_h<2>(acc, b2, A_h, tid);

    // GEMM3: [64,256] x W3[256,128] -> +b3 -> scatter-add
    do_gemm_g<2, HD, ND, LDA_H>(A_h, (const uint2*)g_W3h, acc, tid);
    #pragma unroll
    for (int mt = 0; mt < 2; mt++) {
        int r0 = wm * 32 + mt * 16 + (l >> 2);
        int r1 = r0 + 8;
        bool ok0 = (e0 + r0) < E, ok1 = (e0 + r1) < E;
        float* dst0 = g_aggr + (size_t)col_s[r0] * ND;
        float* dst1 = g_aggr + (size_t)col_s[r1] * ND;
        #pragma unroll
        for (int nt = 0; nt < 4; nt++) {
            int c0 = (wn * 4 + nt) * 8 + (l & 3) * 2;
            float bb0 = b3[c0], bb1 = b3[c0 + 1];
            if (ok0) {
                atomicAdd(dst0 + c0,     acc[mt][nt][0] + bb0);
                atomicAdd(dst0 + c0 + 1, acc[mt][nt][1] + bb1);
            }
            if (ok1) {
                atomicAdd(dst1 + c0,     acc[mt][nt][2] + bb0);
                atomicAdd(dst1 + c0 + 1, acc[mt][nt][3] + bb1);
            }
        }
    }
}

// Precompute P = x@W1a, Q = x@W1b per 128-node tile (fp16 out; bias added later).
__global__ __launch_bounds__(NTE, 1) void pre_kernel(const float* __restrict__ x, int Nn)
{
    extern __shared__ char smem_c[];
    __half* A_h = (__half*)smem_c;                        // [TE][LDA_HP]

    const int tid = threadIdx.x;
    const int l = tid & 31, wid = tid >> 5;
    const int wm = wid & 1, wn = wid >> 1;
    const int n0 = blockIdx.x * TE;

    for (int t = tid; t < TE * 32; t += NTE) {
        int r = t >> 5, j = t & 31;
        int n = n0 + r; if (n >= Nn) n = Nn - 1;
        float4 v = ((const float4*)(x + (size_t)n * ND))[j];
        __half* d = A_h + r * LDA_HP + j * 4;
        *(half2*)(d)     = __floats2half2_rn(v.x, v.y);
        *(half2*)(d + 2) = __floats2half2_rn(v.z, v.w);
    }
    __syncthreads();

    float acc[4][8][4];
    #pragma unroll 1
    for (int which = 0; which < 2; which++) {
        do_gemm_g<4, ND, HD, LDA_HP>(A_h, which ? (const uint2*)g_W1bh : (const uint2*)g_W1ah,
                                     acc, tid);
        __half* O = which ? g_Qh : g_Ph;
        #pragma unroll
        for (int mt = 0; mt < 4; mt++) {
            int r0 = wm * 64 + mt * 16 + (l >> 2);
            int nr0 = n0 + r0, nr1 = nr0 + 8;
            #pragma unroll
            for (int nt = 0; nt < 8; nt++) {
                int c0 = (wn * 8 + nt) * 8 + (l & 3) * 2;
                if (nr0 < Nn) *(half2*)(O + (size_t)nr0 * HD + c0) =
                    __floats2half2_rn(acc[mt][nt][0], acc[mt][nt][1]);
                if (nr1 < Nn) *(half2*)(O + (size_t)nr1 * HD + c0) =
                    __floats2half2_rn(acc[mt][nt][2], acc[mt][nt][3]);
            }
        }
    }
}

// Node pipeline (fp16 MMA): [x|aggr] -> relu(.@Wn1+bn1) -> .@Wn2+bn2 -> +x -> LayerNorm.
__global__ __launch_bounds__(NTE, 1) void node_kernel(
    const float* __restrict__ x,
    const float* __restrict__ bn1, const float* __restrict__ bn2,
    const float* __restrict__ gamma, const float* __restrict__ beta,
    float* __restrict__ out, int Nn)
{
    extern __shared__ char smem_c[];
    __half* A_h = (__half*)smem_c;                        // [TE][LDA_H]
    float*  y_s = (float*)smem_c;                         // [TE][LDY] fp32, aliases A_h

    const int tid = threadIdx.x;
    const int l = tid & 31, wid = tid >> 5;
    const int wm = wid & 1, wn = wid >> 1;
    const int n0 = blockIdx.x * TE;

    for (int t = tid; t < TE * 64; t += NTE) {
        int r = t >> 6, j = t & 63;
        int n = n0 + r; if (n >= Nn) n = Nn - 1;
        float4 v = (j < 32) ? ((const float4*)(x + (size_t)n * ND))[j]
                            : ((const float4*)(g_aggr + (size_t)n * ND))[j - 32];
        __half* d = A_h + r * LDA_H + j * 4;
        *(half2*)(d)     = __floats2half2_rn(v.x, v.y);
        *(half2*)(d + 2) = __floats2half2_rn(v.z, v.w);
    }
    __syncthreads();

    float acc[4][8][4];

    // GEMM_n1: [128,256] x Wn1 -> relu -> A_h
    do_gemm_g<4, HD, HD, LDA_H>(A_h, (const uint2*)g_Wn1h, acc, tid);
    epi_relu_h<4>(acc, bn1, A_h, tid);

    // GEMM_n2: [128,256] x Wn2[256,128] -> +bn2 +x -> y_s fp32
    do_gemm_g<4, HD, ND, LDA_H>(A_h, (const uint2*)g_Wn2h, acc, tid);
    #pragma unroll
    for (int mt = 0; mt < 4; mt++) {
        int r0 = wm * 64 + mt * 16 + (l >> 2);
        int r1 = r0 + 8;
        int nr0 = n0 + r0; if (nr0 >= Nn) nr0 = Nn - 1;
        int nr1 = n0 + r1; if (nr1 >= Nn) nr1 = Nn - 1;
        #pragma unroll
        for (int nt = 0; nt < 4; nt++) {
            int c0 = (wn * 4 + nt) * 8 + (l & 3) * 2;
            float2 x0 = *(const float2*)(x + (size_t)nr0 * ND + c0);
            float2 x1 = *(const float2*)(x + (size_t)nr1 * ND + c0);
            float bb0 = bn2[c0], bb1 = bn2[c0 + 1];
            y_s[r0 * LDY + c0]     = acc[mt][nt][0] + bb0 + x0.x;
            y_s[r0 * LDY + c0 + 1] = acc[mt][nt][1] + bb1 + x0.y;
            y_s[r1 * LDY + c0]     = acc[mt][nt][2] + bb0 + x1.x;
            y_s[r1 * LDY + c0 + 1] = acc[mt][nt][3] + bb1 + x1.y;
        }
    }
    __syncthreads();

    // LayerNorm: warp wid handles rows wid*16 .. wid*16+15
    #pragma unroll 1
    for (int rr = 0; rr < 16; rr++) {
        int r = wid * 16 + rr;
        float4 v = *(const float4*)(y_s + r * LDY + l * 4);
        float s  = v.x + v.y + v.z + v.w;
        float sq = v.x * v.x + v.y * v.y + v.z * v.z + v.w * v.w;
        #pragma unroll
        for (int o = 16; o > 0; o >>= 1) {
            s  += __shfl_xor_sync(0xffffffffu, s, o);
            sq += __shfl_xor_sync(0xffffffffu, sq, o);
        }
        float mean = s * (1.0f / ND);
        float var  = sq * (1.0f / ND) - mean * mean;
        float rstd = rsqrtf(var + 1e-5f);
        int n = n0 + r;
        if (n < Nn) {
            float4 g  = ((const float4*)gamma)[l];
            float4 bb = ((const float4*)beta)[l];
            float4 o4;
            o4.x = (v.x - mean) * rstd * g.x + bb.x;
            o4.y = (v.y - mean) * rstd * g.y + bb.y;
            o4.z = (v.z - mean) * rstd * g.z + bb.z;
            o4.w = (v.w - mean) * rstd * g.w + bb.w;
            ((float4*)(out + (size_t)n * ND))[l] = o4;
        }
    }
}

extern "C" void kernel_launch(void* const* d_in, const int* in_sizes, int n_in,
                              void* d_out, int out_size) {
    const float* x   = (const float*)d_in[0];
    const int*   ei  = (const int*)d_in[1];
    const float* ea  = (const float*)d_in[2];
    const float* W1  = (const float*)d_in[3];
    const float* b1  = (const float*)d_in[4];
    const float* W2  = (const float*)d_in[5];
    const float* b2  = (const float*)d_in[6];
    const float* W3  = (const float*)d_in[7];
    const float* b3  = (const float*)d_in[8];
    const float* Wn1 = (const float*)d_in[9];
    const float* bn1 = (const float*)d_in[10];
    const float* Wn2 = (const float*)d_in[11];
    const float* bn2 = (const float*)d_in[12];
    const float* gm  = (const float*)d_in[13];
    const float* bt  = (const float*)d_in[14];
    float* out = (float*)d_out;

    const int N = in_sizes[0] / ND;
    const int E = in_sizes[1] / 2;

    const int EDGE_SMEM = TE_E * LDA_H * 2 + 2 * TE_E * 4;  // ~34.3 KB (2 CTAs/SM)
    const int PRE_SMEM  = TE * LDA_HP * 2;                  // ~34.8 KB
    const int NODE_SMEM = TE * LDA_H * 2;                   // ~67.6 KB
    cudaFuncSetAttribute(edge_kernel, cudaFuncAttributeMaxDynamicSharedMemorySize, EDGE_SMEM);
    cudaFuncSetAttribute(pre_kernel,  cudaFuncAttributeMaxDynamicSharedMemorySize, PRE_SMEM);
    cudaFuncSetAttribute(node_kernel, cudaFuncAttributeMaxDynamicSharedMemorySize, NODE_SMEM);

    int zero_blocks = (N * ND + 255) / 256;
    if (zero_blocks > 4096) zero_blocks = 4096;

    zero_kernel<<<zero_blocks, 256>>>(N * ND);
    perm_all<<<(67584 + 255) / 256, 256>>>(W1, W2, W3, Wn1, Wn2);
    pre_kernel<<<(N + TE - 1) / TE, NTE, PRE_SMEM>>>(x, N);
    edge_kernel<<<(E + TE_E - 1) / TE_E, NTE, EDGE_SMEM>>>(x, ei, ea, b1, b2, b3, E);
    node_kernel<<<(N + TE - 1) / TE, NTE, NODE_SMEM>>>(x, bn1, bn2, gm, bt, out, N);
}